// round 1
// baseline (speedup 1.0000x reference)
#include <cuda_runtime.h>

#define L_  128
#define J_  24
#define M_  112
#define N_  112
#define I_  14
#define KH_ 9
#define KO_ 24
#define MTILE 4
#define NTHREADS 448

__global__ __launch_bounds__(NTHREADS)
void fused_shiftconv_kernel(const float* __restrict__ x,
                            const float* __restrict__ w1,
                            const float* __restrict__ w2,
                            float* __restrict__ out) {
    // Shared memory
    __shared__ __align__(16) float w1s[KO_][KH_][16];  // w1 padded i->16 (13.5 KB)
    __shared__ float w2s[J_][2][I_];                   // 2.6 KB
    __shared__ float xs[J_][N_];                       // 10.5 KB
    __shared__ __align__(16) float rs[121][20];        // r rows, 20-float pitch (9.5 KB)
    __shared__ __align__(16) float p1sp[9][16];        // special p1 rows for n==0 fix

    const int tid = threadIdx.x;
    const int b   = blockIdx.x;
    const int l   = b / (M_ / MTILE);
    const int m0  = (b % (M_ / MTILE)) * MTILE;

    // Load weights once per block (L2-cached; ~15 KB per block)
    for (int idx = tid; idx < KO_ * KH_ * 16; idx += NTHREADS) {
        int k  = idx / (KH_ * 16);
        int rem = idx % (KH_ * 16);
        int kh = rem / 16;
        int i  = rem % 16;
        w1s[k][kh][i] = (i < I_) ? w1[(k * KH_ + kh) * I_ + i] : 0.0f;
    }
    for (int idx = tid; idx < J_ * 2 * I_; idx += NTHREADS)
        ((float*)w2s)[idx] = w2[idx];

    const int h     = tid % N_;   // pixel index along n (also output n in phase C)
    const int ig    = tid / N_;   // 0..3
    const int kbase = ig * 6;     // phase C: 6 output channels per thread

    for (int mt = 0; mt < MTILE; mt++) {
        const int m = m0 + mt;
        __syncthreads();  // protect xs/rs reuse across mt iterations

        // Zero r buffer + p1 specials; stage x row into smem
        for (int idx = tid; idx < 121 * 20; idx += NTHREADS) ((float*)rs)[idx]   = 0.0f;
        for (int idx = tid; idx < 9 * 16;  idx += NTHREADS) ((float*)p1sp)[idx] = 0.0f;
        for (int idx = tid; idx < J_ * N_; idx += NTHREADS) {
            int j  = idx / N_;
            int hh = idx % N_;
            xs[j][hh] = x[((l * J_ + j) * M_ + m) * N_ + hh];
        }
        __syncthreads();

        // ---- Phase B: p0/p1 projection, build r = p0[h] + p1[h-1] (zero-extended) ----
        float a0[4];
        const int i0 = ig * 4;
        const int ni = (ig == 3) ? 2 : 4;   // i: ig*4 .. min(ig*4+4, 14)
        {
            float xv[J_];
            #pragma unroll
            for (int j = 0; j < J_; j++) xv[j] = xs[j][h];

            #pragma unroll
            for (int t = 0; t < 4; t++) {
                if (t < ni) {
                    const int i = i0 + t;
                    float s0 = 0.0f, s1 = 0.0f;
                    #pragma unroll
                    for (int j = 0; j < J_; j++) {
                        s0 = fmaf(xv[j], w2s[j][0][i], s0);
                        s1 = fmaf(xv[j], w2s[j][1][i], s1);
                    }
                    a0[t] = s0;
                    rs[h + 5][i] = s1;                     // p1[h] feeds r[h+1]
                    if (h < 4)    p1sp[h][i]       = s1;   // p1[0..3]   (kh>=5 correction)
                    if (h >= 107) p1sp[h - 103][i] = s1;   // p1[107..111] (kh<=4 correction)
                }
            }
        }
        __syncthreads();
        #pragma unroll
        for (int t = 0; t < 4; t++) {
            if (t < ni) rs[h + 4][i0 + t] += a0[t];        // p0[h] feeds r[h]
        }
        __syncthreads();

        // ---- Phase C: 9-tap x 14-chan conv of r against w1 ----
        float acc[6];
        #pragma unroll
        for (int kk = 0; kk < 6; kk++) acc[kk] = 0.0f;

        #pragma unroll
        for (int kh = 0; kh < KH_; kh++) {
            const float4* rr = (const float4*)rs[h + kh];  // r[(n+kh-4)] (80B pitch, conflict-free)
            float4 r0 = rr[0], r1 = rr[1], r2 = rr[2], r3 = rr[3];
            #pragma unroll
            for (int kk = 0; kk < 6; kk++) {
                const float4* wr = (const float4*)w1s[kbase + kk][kh];  // broadcast
                float4 q0 = wr[0], q1 = wr[1], q2 = wr[2], q3 = wr[3];
                float a = acc[kk];
                a = fmaf(r0.x, q0.x, a); a = fmaf(r0.y, q0.y, a);
                a = fmaf(r0.z, q0.z, a); a = fmaf(r0.w, q0.w, a);
                a = fmaf(r1.x, q1.x, a); a = fmaf(r1.y, q1.y, a);
                a = fmaf(r1.z, q1.z, a); a = fmaf(r1.w, q1.w, a);
                a = fmaf(r2.x, q2.x, a); a = fmaf(r2.y, q2.y, a);
                a = fmaf(r2.z, q2.z, a); a = fmaf(r2.w, q2.w, a);
                a = fmaf(r3.x, q3.x, a); a = fmaf(r3.y, q3.y, a);
                a = fmaf(r3.z, q3.z, a); a = fmaf(r3.w, q3.w, a);
                acc[kk] = a;
            }
        }

        // n == 0 wrap-around correction (roll is cyclic over the merged (n,k2) axis)
        if (h == 0) {
            #pragma unroll
            for (int kh = 0; kh < KH_; kh++) {
                const int  slot = (kh <= 4) ? (4 + kh) : (kh - 5);
                const float sgn = (kh <= 4) ? 1.0f : -1.0f;
                const float4* pr = (const float4*)p1sp[slot];
                float4 p0v = pr[0], p1v = pr[1], p2v = pr[2], p3v = pr[3];
                #pragma unroll
                for (int kk = 0; kk < 6; kk++) {
                    const float4* wr = (const float4*)w1s[kbase + kk][kh];
                    float4 q0 = wr[0], q1 = wr[1], q2 = wr[2], q3 = wr[3];
                    float s = p0v.x*q0.x + p0v.y*q0.y + p0v.z*q0.z + p0v.w*q0.w
                            + p1v.x*q1.x + p1v.y*q1.y + p1v.z*q1.z + p1v.w*q1.w
                            + p2v.x*q2.x + p2v.y*q2.y + p2v.z*q2.z + p2v.w*q2.w
                            + p3v.x*q3.x + p3v.y*q3.y + p3v.z*q3.z + p3v.w*q3.w;
                    acc[kk] += sgn * s;
                }
            }
        }

        // Coalesced store: out[l, k, m, n]
        #pragma unroll
        for (int kk = 0; kk < 6; kk++)
            out[((l * KO_ + kbase + kk) * M_ + m) * N_ + h] = acc[kk];
    }
}

extern "C" void kernel_launch(void* const* d_in, const int* in_sizes, int n_in,
                              void* d_out, int out_size) {
    const float* x  = (const float*)d_in[0];
    const float* w1 = (const float*)d_in[1];
    const float* w2 = (const float*)d_in[2];
    // Defensive: w1 has 3024 elements, w2 has 672 — swap if order differs.
    if (n_in >= 3 && in_sizes[1] == 672 && in_sizes[2] == 3024) {
        const float* t = w1; w1 = w2; w2 = t;
    }
    float* out = (float*)d_out;

    dim3 grid(L_ * (M_ / MTILE));
    fused_shiftconv_kernel<<<grid, NTHREADS>>>(x, w1, w2, out);
}

// round 3
// speedup vs baseline: 12.9720x; 12.9720x over previous
#include <cuda_runtime.h>

#define L_    128
#define J_    24
#define NPIX  112
#define I_    14
#define KH_   9
#define KO_   24
#define MT    4        // m-rows per block
#define RP    120      // rst row pitch (floats), 480B (16B-aligned)
#define NTH   672

__global__ __launch_bounds__(NTH, 1)
void fused_shiftconv2(const float* __restrict__ x,
                      const float* __restrict__ w1,
                      const float* __restrict__ w2,
                      float* __restrict__ out) {
    // r buffer, transposed: rst[m][i][col], col = padded conv coordinate
    __shared__ __align__(16) float rst[MT][I_][RP];       // 26.25 KB
    __shared__ __align__(16) float w1t[KH_][I_][KO_];     // [kh][i][k]  11.8 KB
    __shared__ __align__(16) float w2s[J_][2][16];        // i padded to 16  6 KB
    __shared__ float p1sp[MT][9][I_];                     // n==0 wrap fix   2 KB
    // total 47,136 B static shared (< 48 KB cap)

    const int t  = threadIdx.x;
    const int l  = blockIdx.x / 28;
    const int m0 = (blockIdx.x % 28) * MT;

    // ---- preamble: weights to smem, zero r buffer ----
    for (int idx = t; idx < KH_ * I_ * KO_; idx += NTH) {
        int kh = idx / (I_ * KO_);
        int rem = idx % (I_ * KO_);
        int i = rem / KO_, k = rem % KO_;
        w1t[kh][i][k] = w1[(k * KH_ + kh) * I_ + i];
    }
    for (int idx = t; idx < J_ * 2 * 16; idx += NTH) {
        int j = idx / 32, rem = idx % 32;
        int sel = rem / 16, i = rem % 16;
        w2s[j][sel][i] = (i < I_) ? w2[(j * 2 + sel) * I_ + i] : 0.0f;
    }
    for (int idx = t; idx < MT * I_ * RP; idx += NTH)
        ((float*)rst)[idx] = 0.0f;
    __syncthreads();

    // ---- Phase B: projection p0/p1, build r[col] = p0[col-4] + p1[col-5] ----
    const bool act = (t < MT * NPIX);
    float s0[I_], s1[I_];
    int bms = 0, bh = 0;
    if (act) {
        bms = t / NPIX;
        bh  = t % NPIX;
        const int m = m0 + bms;
        #pragma unroll
        for (int i = 0; i < I_; i++) { s0[i] = 0.0f; s1[i] = 0.0f; }
        const float* xp = x + ((size_t)(l * J_) * NPIX + m) * NPIX + bh;
        #pragma unroll
        for (int j = 0; j < J_; j++) {
            float xv = xp[j * (NPIX * NPIX)];
            float wb[16], wc[16];
            const float4* q0 = (const float4*)w2s[j][0];
            const float4* q1 = (const float4*)w2s[j][1];
            *(float4*)(wb + 0) = q0[0]; *(float4*)(wb + 4)  = q0[1];
            *(float4*)(wb + 8) = q0[2]; *(float4*)(wb + 12) = q0[3];
            *(float4*)(wc + 0) = q1[0]; *(float4*)(wc + 4)  = q1[1];
            *(float4*)(wc + 8) = q1[2]; *(float4*)(wc + 12) = q1[3];
            #pragma unroll
            for (int i = 0; i < I_; i++) {
                s0[i] = fmaf(xv, wb[i], s0[i]);
                s1[i] = fmaf(xv, wc[i], s1[i]);
            }
        }
        // p1[h] -> col h+5 ; save edge rows for the n==0 cyclic correction
        #pragma unroll
        for (int i = 0; i < I_; i++) rst[bms][i][bh + 5] = s1[i];
        if (bh < 4) {
            #pragma unroll
            for (int i = 0; i < I_; i++) p1sp[bms][bh][i] = s1[i];
        }
        if (bh >= 107) {
            #pragma unroll
            for (int i = 0; i < I_; i++) p1sp[bms][bh - 103][i] = s1[i];
        }
    }
    __syncthreads();
    if (act) {
        // p0[h] -> col h+4 (add onto p1 term written by neighbor thread)
        #pragma unroll
        for (int i = 0; i < I_; i++) rst[bms][i][bh + 4] += s0[i];
    }
    __syncthreads();

    // ---- Phase C: 9-tap x 14-chan conv, 4n x 4k register tile per thread ----
    {
        const int ms  = t / 168;
        const int idx = t % 168;
        const int kg  = idx / 28;      // 6 k-groups
        const int ng  = idx % 28;      // 28 n-groups (lane-fastest -> coalesced stores)
        const int n0  = ng * 4;
        const int k0  = kg * 4;
        const int m   = m0 + ms;
        const bool edge = (ng == 0);

        float acc[4][4];
        #pragma unroll
        for (int a = 0; a < 4; a++)
            #pragma unroll
            for (int b = 0; b < 4; b++) acc[a][b] = 0.0f;

        #pragma unroll
        for (int i = 0; i < I_; i++) {
            const float* rrow = &rst[ms][i][n0];
            float ra[12];
            *(float4*)(ra + 0) = *(const float4*)(rrow + 0);
            *(float4*)(ra + 4) = *(const float4*)(rrow + 4);
            *(float4*)(ra + 8) = *(const float4*)(rrow + 8);
            #pragma unroll
            for (int kh = 0; kh < KH_; kh++) {
                float4 wv = *(const float4*)&w1t[kh][i][k0];
                #pragma unroll
                for (int dn = 0; dn < 4; dn++) {
                    float rv = ra[dn + kh];
                    acc[dn][0] = fmaf(rv, wv.x, acc[dn][0]);
                    acc[dn][1] = fmaf(rv, wv.y, acc[dn][1]);
                    acc[dn][2] = fmaf(rv, wv.z, acc[dn][2]);
                    acc[dn][3] = fmaf(rv, wv.w, acc[dn][3]);
                }
                if (edge) {
                    // cyclic roll wrap: affects only n==0
                    const int  slot = (kh <= 4) ? (kh + 4) : (kh - 5);
                    const float sgn = (kh <= 4) ? 1.0f : -1.0f;
                    float pv = sgn * p1sp[ms][slot][i];
                    acc[0][0] = fmaf(pv, wv.x, acc[0][0]);
                    acc[0][1] = fmaf(pv, wv.y, acc[0][1]);
                    acc[0][2] = fmaf(pv, wv.z, acc[0][2]);
                    acc[0][3] = fmaf(pv, wv.w, acc[0][3]);
                }
            }
        }

        // store: out[l, k0+kk, m, n0..n0+3] as STG.128, lane-consecutive in n
        float* op = out + (((size_t)l * KO_ + k0) * NPIX + m) * NPIX + n0;
        #pragma unroll
        for (int kk = 0; kk < 4; kk++) {
            float4 v = make_float4(acc[0][kk], acc[1][kk], acc[2][kk], acc[3][kk]);
            *(float4*)(op + kk * (NPIX * NPIX)) = v;
        }
    }
}

extern "C" void kernel_launch(void* const* d_in, const int* in_sizes, int n_in,
                              void* d_out, int out_size) {
    const float* x  = (const float*)d_in[0];
    const float* w1 = (const float*)d_in[1];
    const float* w2 = (const float*)d_in[2];
    if (n_in >= 3 && in_sizes[1] == 672 && in_sizes[2] == 3024) {
        const float* tmp = w1; w1 = w2; w2 = tmp;
    }
    float* out = (float*)d_out;

    dim3 grid(L_ * 28);
    fused_shiftconv2<<<grid, NTH>>>(x, w1, w2, out);
}

// round 6
// speedup vs baseline: 21.7703x; 1.6782x over previous
#include <cuda_runtime.h>
#include <cstdint>

#define L_    128
#define J_    24
#define NPIX  112
#define I_    14
#define KH_   9
#define KO_   24
#define MT    4
#define RCP   15           // rc row pitch (floats)
#define NTH   448

__device__ __forceinline__ uint32_t f2tf32(float f) {
    uint32_t u;
    asm("cvt.rna.tf32.f32 %0, %1;" : "=r"(u) : "f"(f));
    return u;
}

__device__ __forceinline__ void mma_tf32(float* d, const uint32_t* a, const uint32_t* b) {
    asm volatile(
        "mma.sync.aligned.m16n8k8.row.col.f32.tf32.tf32.f32 "
        "{%0,%1,%2,%3}, {%4,%5,%6,%7}, {%8,%9}, {%0,%1,%2,%3};"
        : "+f"(d[0]), "+f"(d[1]), "+f"(d[2]), "+f"(d[3])
        : "r"(a[0]), "r"(a[1]), "r"(a[2]), "r"(a[3]), "r"(b[0]), "r"(b[1]));
}

__global__ __launch_bounds__(NTH, 2)
void fused_shiftconv_mma(const float* __restrict__ x,
                         const float* __restrict__ w1,
                         const float* __restrict__ w2,
                         float* __restrict__ out) {
    __shared__ __align__(16) float rc[MT][121][RCP];   // 29,040 B  (padded conv rows)
    __shared__ __align__(16) uint32_t w1t[128][KO_];   // 12,288 B  (tf32-rounded, [kq][k])
    __shared__ __align__(16) float w2s[J_][2][16];     //  3,072 B
    __shared__ float p1s[MT][9][I_];                   //  2,016 B
    __shared__ float corr[MT][KO_];                    //    384 B   => 46,800 B total

    const int t    = threadIdx.x;
    const int lane = t & 31;
    const int wid  = t >> 5;
    const int l    = blockIdx.x / 28;
    const int m0   = (blockIdx.x % 28) * MT;

    // ---- preamble: weights to smem (w1 tf32-rounded), zero rc ----
    for (int idx = t; idx < 128 * KO_; idx += NTH) {
        int kq = idx / KO_, k = idx % KO_;
        float v = (kq < 126) ? w1[k * 126 + kq] : 0.0f;
        w1t[kq][k] = f2tf32(v);
    }
    for (int idx = t; idx < J_ * 2 * 16; idx += NTH) {
        int j = idx >> 5, rem = idx & 31;
        int sel = rem >> 4, i = rem & 15;
        w2s[j][sel][i] = (i < I_) ? w2[(j * 2 + sel) * I_ + i] : 0.0f;
    }
    for (int idx = t; idx < MT * 121 * RCP; idx += NTH)
        ((float*)rc)[idx] = 0.0f;
    __syncthreads();

    // ---- Phase B: fp32 projection; rc[col] = p0[col-4] + p1[col-5] ----
    {
        const int ms = t / NPIX;        // 448 = MT*NPIX exactly
        const int h  = t % NPIX;
        const int m  = m0 + ms;
        float s0[I_], s1[I_];
        #pragma unroll
        for (int i = 0; i < I_; i++) { s0[i] = 0.0f; s1[i] = 0.0f; }
        const float* xp = x + ((size_t)(l * J_) * NPIX + m) * NPIX + h;
        #pragma unroll
        for (int j = 0; j < J_; j++) {
            float xv = xp[j * (NPIX * NPIX)];
            float wb[16], wc[16];
            const float4* q0 = (const float4*)w2s[j][0];
            const float4* q1 = (const float4*)w2s[j][1];
            *(float4*)(wb + 0) = q0[0]; *(float4*)(wb + 4)  = q0[1];
            *(float4*)(wb + 8) = q0[2]; *(float4*)(wb + 12) = q0[3];
            *(float4*)(wc + 0) = q1[0]; *(float4*)(wc + 4)  = q1[1];
            *(float4*)(wc + 8) = q1[2]; *(float4*)(wc + 12) = q1[3];
            #pragma unroll
            for (int i = 0; i < I_; i++) {
                s0[i] = fmaf(xv, wb[i], s0[i]);
                s1[i] = fmaf(xv, wc[i], s1[i]);
            }
        }
        #pragma unroll
        for (int i = 0; i < I_; i++) rc[ms][h + 5][i] = s1[i];   // p1[h] -> col h+5
        if (h < 4) {
            #pragma unroll
            for (int i = 0; i < I_; i++) p1s[ms][h][i] = s1[i];
        }
        if (h >= 107) {
            #pragma unroll
            for (int i = 0; i < I_; i++) p1s[ms][h - 103][i] = s1[i];
        }
        __syncthreads();
        #pragma unroll
        for (int i = 0; i < I_; i++) rc[ms][h + 4][i] += s0[i];  // p0[h] -> col h+4
    }
    __syncthreads();

    // ---- n==0 cyclic-wrap correction per (ms, k) ----
    if (t < MT * KO_) {
        const int ms = t / KO_;
        const int k  = t % KO_;
        float c = 0.0f;
        #pragma unroll
        for (int kh = 0; kh < KH_; kh++) {
            const int  slot = (kh <= 4) ? (kh + 4) : (kh - 5);
            const float sgn = (kh <= 4) ? 1.0f : -1.0f;
            const float* pp = p1s[ms][slot];
            const float* ww = w1 + k * 126 + kh * I_;
            float s = 0.0f;
            #pragma unroll
            for (int i = 0; i < I_; i++) s = fmaf(pp[i], ww[i], s);
            c = fmaf(sgn, s, c);
        }
        corr[ms][k] = c;
    }
    __syncthreads();

    // ---- Phase C: tf32 mma.sync GEMM  D[112,24] = A[112,128] x B[128,24] ----
    const int qa = lane & 3;      // k-quad within fragment
    const int ua = lane >> 2;     // row/col group
    int msT[2], rtT[2];
    #pragma unroll
    for (int tt = 0; tt < 2; tt++) {
        int g = wid * 2 + tt;     // global row-tile 0..27
        msT[tt] = g / 7;
        rtT[tt] = g % 7;
    }

    float acc[2][3][4];
    #pragma unroll
    for (int a = 0; a < 2; a++)
        #pragma unroll
        for (int b = 0; b < 3; b++)
            #pragma unroll
            for (int c = 0; c < 4; c++) acc[a][b][c] = 0.0f;

    #pragma unroll
    for (int ks = 0; ks < 16; ks++) {
        const int kq0 = ks * 8 + qa;    // qa runtime, but kh/i split below uses
        const int kq1 = kq0 + 4;        //  per-qa constant tables via unrolled ks
        // B fragments (conflict-free; already tf32-rounded)
        uint32_t bf[3][2];
        #pragma unroll
        for (int nt = 0; nt < 3; nt++) {
            bf[nt][0] = w1t[kq0][nt * 8 + ua];
            bf[nt][1] = w1t[kq1][nt * 8 + ua];
        }
        const int kh0 = kq0 / I_, i0 = kq0 - kh0 * I_;
        const int kh1 = kq1 / I_, i1 = kq1 - kh1 * I_;
        #pragma unroll
        for (int tt = 0; tt < 2; tt++) {
            const float* base = &rc[msT[tt]][0][0];
            const int p = rtT[tt] * 16 + ua;
            uint32_t af[4];
            af[0] = f2tf32(base[(p + kh0) * RCP + i0]);
            af[1] = f2tf32(base[(p + 8 + kh0) * RCP + i0]);
            af[2] = f2tf32(base[(p + kh1) * RCP + i1]);
            af[3] = f2tf32(base[(p + 8 + kh1) * RCP + i1]);
            #pragma unroll
            for (int nt = 0; nt < 3; nt++)
                mma_tf32(acc[tt][nt], af, bf[nt]);
        }
    }

    // ---- epilogue: direct stores (sector-aligned: 8 consecutive pixels/quad) ----
    #pragma unroll
    for (int tt = 0; tt < 2; tt++) {
        const int m = m0 + msT[tt];
        const int p = rtT[tt] * 16 + ua;
        const bool edge = (rtT[tt] == 0 && ua == 0);   // p == 0
        #pragma unroll
        for (int nt = 0; nt < 3; nt++) {
            const int k0 = nt * 8 + 2 * qa;
            float c0 = acc[tt][nt][0], c1 = acc[tt][nt][1];
            float c2 = acc[tt][nt][2], c3 = acc[tt][nt][3];
            if (edge) { c0 += corr[msT[tt]][k0]; c1 += corr[msT[tt]][k0 + 1]; }
            float* o0 = out + (((size_t)l * KO_ + k0) * NPIX + m) * NPIX + p;
            float* o1 = out + (((size_t)l * KO_ + k0 + 1) * NPIX + m) * NPIX + p;
            o0[0] = c0;
            o1[0] = c1;
            o0[8] = c2;
            o1[8] = c3;
        }
    }
}

extern "C" void kernel_launch(void* const* d_in, const int* in_sizes, int n_in,
                              void* d_out, int out_size) {
    const float* x  = (const float*)d_in[0];
    const float* w1 = (const float*)d_in[1];
    const float* w2 = (const float*)d_in[2];
    if (n_in >= 3 && in_sizes[1] == 672 && in_sizes[2] == 3024) {
        const float* tmp = w1; w1 = w2; w2 = tmp;
    }
    float* out = (float*)d_out;

    dim3 grid(L_ * 28);
    fused_shiftconv_mma<<<grid, NTH>>>(x, w1, w2, out);
}

// round 7
// speedup vs baseline: 22.6512x; 1.0405x over previous
#include <cuda_runtime.h>
#include <cstdint>

#define L_    128
#define J_    24
#define NPIX  112
#define I_    14
#define KH_   9
#define KO_   24
#define MT    4
#define RCP   15           // rc row pitch (words)
#define NTH   448

__device__ __forceinline__ uint32_t f2tf32(float f) {
    uint32_t u;
    asm("cvt.rna.tf32.f32 %0, %1;" : "=r"(u) : "f"(f));
    return u;
}

__device__ __forceinline__ void mma_tf32(float* d, const uint32_t* a, const uint32_t* b) {
    asm volatile(
        "mma.sync.aligned.m16n8k8.row.col.f32.tf32.tf32.f32 "
        "{%0,%1,%2,%3}, {%4,%5,%6,%7}, {%8,%9}, {%0,%1,%2,%3};"
        : "+f"(d[0]), "+f"(d[1]), "+f"(d[2]), "+f"(d[3])
        : "r"(a[0]), "r"(a[1]), "r"(a[2]), "r"(a[3]), "r"(b[0]), "r"(b[1]));
}

__global__ __launch_bounds__(NTH, 2)
void fused_shiftconv_mma3(const float* __restrict__ x,
                          const float* __restrict__ w1,
                          const float* __restrict__ w2,
                          float* __restrict__ out) {
    __shared__ __align__(16) uint32_t rc[MT][121][RCP]; // 29,040 B  tf32 bits, pre-converted
    __shared__ __align__(16) uint32_t w1t[128][KO_];    // 12,288 B  tf32 [kq][k]
    __shared__ __align__(16) float w2s[J_][2][16];      //  3,072 B
    __shared__ float p1s[MT][9][I_];                    //  2,016 B
    __shared__ float wb[14][16];                        //    896 B  warp-boundary p1 exchange
    __shared__ float corr[MT][KO_];                     //    384 B  => 47,696 B

    const int t    = threadIdx.x;
    const int lane = t & 31;
    const int wid  = t >> 5;
    const int l    = blockIdx.x / 28;
    const int m0   = (blockIdx.x % 28) * MT;

    // ---- preamble: weights -> smem (tf32), zero rc pad rows {0..3, 117..120} ----
    for (int idx = t; idx < 128 * KO_; idx += NTH) {
        int kq = idx / KO_, k = idx % KO_;
        float v = (kq < 126) ? w1[k * 126 + kq] : 0.0f;
        w1t[kq][k] = f2tf32(v);
    }
    for (int idx = t; idx < J_ * 2 * 16; idx += NTH) {
        int j = idx >> 5, rem = idx & 31;
        int sel = rem >> 4, i = rem & 15;
        w2s[j][sel][i] = (i < I_) ? w2[(j * 2 + sel) * I_ + i] : 0.0f;
    }
    for (int idx = t; idx < MT * 8 * RCP; idx += NTH) {
        int ms  = idx / (8 * RCP);
        int rem = idx % (8 * RCP);
        int rr  = rem / RCP;            // 0..7 -> rows {0..3, 117..120}
        int i   = rem % RCP;
        int row = (rr < 4) ? rr : (113 + rr);
        rc[ms][row][i] = 0u;
    }
    __syncthreads();

    // ---- Phase B: fp32 projection; r[h+4] = p0[h] + p1[h-1], tf32-stored once ----
    {
        const int ms = t / NPIX;        // 448 = MT*NPIX exactly
        const int h  = t % NPIX;
        const int m  = m0 + ms;
        float s0[I_], s1[I_];
        #pragma unroll
        for (int i = 0; i < I_; i++) { s0[i] = 0.0f; s1[i] = 0.0f; }
        const float* xp = x + ((size_t)(l * J_) * NPIX + m) * NPIX + h;
        #pragma unroll
        for (int j = 0; j < J_; j++) {
            float xv = xp[j * (NPIX * NPIX)];
            float wbv[16], wcv[16];
            const float4* q0 = (const float4*)w2s[j][0];
            const float4* q1 = (const float4*)w2s[j][1];
            *(float4*)(wbv + 0) = q0[0]; *(float4*)(wbv + 4)  = q0[1];
            *(float4*)(wbv + 8) = q0[2]; *(float4*)(wbv + 12) = q0[3];
            *(float4*)(wcv + 0) = q1[0]; *(float4*)(wcv + 4)  = q1[1];
            *(float4*)(wcv + 8) = q1[2]; *(float4*)(wcv + 12) = q1[3];
            #pragma unroll
            for (int i = 0; i < I_; i++) {
                s0[i] = fmaf(xv, wbv[i], s0[i]);
                s1[i] = fmaf(xv, wcv[i], s1[i]);
            }
        }
        // boundary exchange + edge saves
        if (lane == 31) {
            #pragma unroll
            for (int i = 0; i < I_; i++) wb[wid][i] = s1[i];
        }
        if (h < 4) {
            #pragma unroll
            for (int i = 0; i < I_; i++) p1s[ms][h][i] = s1[i];
        }
        if (h >= 107) {
            #pragma unroll
            for (int i = 0; i < I_; i++) p1s[ms][h - 103][i] = s1[i];
        }
        __syncthreads();

        float p1p[I_];
        #pragma unroll
        for (int i = 0; i < I_; i++) p1p[i] = __shfl_up_sync(0xffffffffu, s1[i], 1);
        if (lane == 0 && wid > 0) {
            #pragma unroll
            for (int i = 0; i < I_; i++) p1p[i] = wb[wid - 1][i];
        }
        if (h == 0) {
            #pragma unroll
            for (int i = 0; i < I_; i++) p1p[i] = 0.0f;
        }
        uint32_t* row = rc[ms][h + 4];
        #pragma unroll
        for (int i = 0; i < I_; i++) row[i] = f2tf32(s0[i] + p1p[i]);
        if (h == 111) {
            uint32_t* r116 = rc[ms][116];
            #pragma unroll
            for (int i = 0; i < I_; i++) r116[i] = f2tf32(s1[i]);
        }
    }

    // ---- n==0 cyclic-wrap correction per (ms, k) (p1s ready since sync above) ----
    if (t < MT * KO_) {
        const int ms = t / KO_;
        const int k  = t % KO_;
        float c = 0.0f;
        #pragma unroll
        for (int kh = 0; kh < KH_; kh++) {
            const int  slot = (kh <= 4) ? (kh + 4) : (kh - 5);
            const float sgn = (kh <= 4) ? 1.0f : -1.0f;
            const float* pp = p1s[ms][slot];
            const float* ww = w1 + k * 126 + kh * I_;
            float s = 0.0f;
            #pragma unroll
            for (int i = 0; i < I_; i++) s = fmaf(pp[i], ww[i], s);
            c = fmaf(sgn, s, c);
        }
        corr[ms][k] = c;
    }
    __syncthreads();

    // ---- Phase C: tf32 mma.sync GEMM  D[112,24] = A[112,128] x B[128,24] ----
    const int qa = lane & 3;
    const int ua = lane >> 2;
    int msT[2], rtT[2];
    #pragma unroll
    for (int tt = 0; tt < 2; tt++) {
        int g = wid * 2 + tt;
        msT[tt] = g / 7;
        rtT[tt] = g % 7;
    }

    float acc[2][3][4];
    #pragma unroll
    for (int a = 0; a < 2; a++)
        #pragma unroll
        for (int b = 0; b < 3; b++)
            #pragma unroll
            for (int c = 0; c < 4; c++) acc[a][b][c] = 0.0f;

    #pragma unroll
    for (int ks = 0; ks < 16; ks++) {
        const int kq0 = ks * 8 + qa;
        const int kq1 = kq0 + 4;
        uint32_t bf[3][2];
        #pragma unroll
        for (int nt = 0; nt < 3; nt++) {
            bf[nt][0] = w1t[kq0][nt * 8 + ua];
            bf[nt][1] = w1t[kq1][nt * 8 + ua];
        }
        const int kh0 = kq0 / I_, i0 = kq0 - kh0 * I_;
        const int kh1 = kq1 / I_, i1 = kq1 - kh1 * I_;
        #pragma unroll
        for (int tt = 0; tt < 2; tt++) {
            const uint32_t* base = &rc[msT[tt]][0][0];
            const int p = rtT[tt] * 16 + ua;
            uint32_t af[4];
            af[0] = base[(p + kh0) * RCP + i0];
            af[1] = base[(p + 8 + kh0) * RCP + i0];
            af[2] = base[(p + kh1) * RCP + i1];
            af[3] = base[(p + 8 + kh1) * RCP + i1];
            #pragma unroll
            for (int nt = 0; nt < 3; nt++)
                mma_tf32(acc[tt][nt], af, bf[nt]);
        }
    }

    // ---- epilogue: direct stores (8 consecutive pixels per quad -> full sectors) ----
    #pragma unroll
    for (int tt = 0; tt < 2; tt++) {
        const int m = m0 + msT[tt];
        const int p = rtT[tt] * 16 + ua;
        const bool edge = (rtT[tt] == 0 && ua == 0);   // p == 0
        #pragma unroll
        for (int nt = 0; nt < 3; nt++) {
            const int k0 = nt * 8 + 2 * qa;
            float c0 = acc[tt][nt][0], c1 = acc[tt][nt][1];
            float c2 = acc[tt][nt][2], c3 = acc[tt][nt][3];
            if (edge) { c0 += corr[msT[tt]][k0]; c1 += corr[msT[tt]][k0 + 1]; }
            float* o0 = out + (((size_t)l * KO_ + k0) * NPIX + m) * NPIX + p;
            float* o1 = out + (((size_t)l * KO_ + k0 + 1) * NPIX + m) * NPIX + p;
            o0[0] = c0;
            o1[0] = c1;
            o0[8] = c2;
            o1[8] = c3;
        }
    }
}

extern "C" void kernel_launch(void* const* d_in, const int* in_sizes, int n_in,
                              void* d_out, int out_size) {
    const float* x  = (const float*)d_in[0];
    const float* w1 = (const float*)d_in[1];
    const float* w2 = (const float*)d_in[2];
    if (n_in >= 3 && in_sizes[1] == 672 && in_sizes[2] == 3024) {
        const float* tmp = w1; w1 = w2; w2 = tmp;
    }
    float* out = (float*)d_out;

    dim3 grid(L_ * 28);
    fused_shiftconv_mma3<<<grid, NTH>>>(x, w1, w2, out);
}